// round 13
// baseline (speedup 1.0000x reference)
#include <cuda_runtime.h>
#include <cuda_bf16.h>
#include <stdint.h>
#include <math.h>

#define B_ 4
#define T_ 4096
#define C_ 1024
#define HD 64

// scratch (no cudaMalloc allowed)
__device__ __nv_bfloat16 g_qh[B_ * T_ * HD];        // Q bf16 [b*t][h]
__device__ __nv_bfloat16 g_kh[B_ * T_ * HD];        // K bf16 [b*t][h]
__device__ float         g_v [B_ * T_ * HD];        // V fp32 [b*t][h]
__device__ __nv_bfloat16 g_vth[B_ * HD * T_];       // V^T hi bf16 [b][h][t]
__device__ __nv_bfloat16 g_vtl[B_ * HD * T_];       // V^T lo
__device__ __nv_bfloat16 g_wth[3 * HD * C_];        // W^T hi bf16 [m][n][k]
__device__ __nv_bfloat16 g_wvl[HD * C_];            // Wv^T lo

// ---------------------------------------------------------------------------
// helpers
// ---------------------------------------------------------------------------
__device__ __forceinline__ uint32_t smem_u32(const void* p) {
    uint32_t a;
    asm("{ .reg .u64 t; cvta.to.shared.u64 t, %1; cvt.u32.u64 %0, t; }"
        : "=r"(a) : "l"(p));
    return a;
}
__device__ __forceinline__ void mma16816(float* c, const uint32_t* a,
                                         uint32_t b0, uint32_t b1) {
    asm volatile(
        "mma.sync.aligned.m16n8k16.row.col.f32.bf16.bf16.f32 "
        "{%0,%1,%2,%3}, {%4,%5,%6,%7}, {%8,%9}, {%0,%1,%2,%3};"
        : "+f"(c[0]), "+f"(c[1]), "+f"(c[2]), "+f"(c[3])
        : "r"(a[0]), "r"(a[1]), "r"(a[2]), "r"(a[3]), "r"(b0), "r"(b1));
}
__device__ __forceinline__ void ldmx4(uint32_t& r0, uint32_t& r1,
                                      uint32_t& r2, uint32_t& r3, uint32_t addr) {
    asm volatile("ldmatrix.sync.aligned.m8n8.x4.shared.b16 {%0,%1,%2,%3}, [%4];"
                 : "=r"(r0), "=r"(r1), "=r"(r2), "=r"(r3) : "r"(addr));
}
__device__ __forceinline__ uint32_t pk_bf16(float lo, float hi) {
    __nv_bfloat162 h = __floats2bfloat162_rn(lo, hi);
    return *(uint32_t*)&h;
}
__device__ __forceinline__ void cpa16(uint32_t saddr, const void* g) {
    asm volatile("cp.async.cg.shared.global [%0], [%1], 16;"
                 :: "r"(saddr), "l"(g) : "memory");
}
#define CPA_COMMIT() asm volatile("cp.async.commit_group;" ::: "memory")
#define CPA_WAIT0()  asm volatile("cp.async.wait_group 0;" ::: "memory")
#define CPA_WAIT1()  asm volatile("cp.async.wait_group 1;" ::: "memory")

// ===========================================================================
// Kernel 0: transpose + bf16-split W -> g_wth [m][n][k], g_wvl (v only)
// ===========================================================================
__global__ __launch_bounds__(256) void prep_w(
    const float* __restrict__ Wq, const float* __restrict__ Wk,
    const float* __restrict__ Wv)
{
    __shared__ float s[64][68];
    const int tid = threadIdx.x;
    const int kc = blockIdx.x;
    const int m = blockIdx.y;
    const float* W = (m == 0) ? Wq : (m == 1) ? Wk : Wv;

    {
        int r = tid >> 2, c0 = (tid & 3) * 16;
        const float* wp = W + ((size_t)(kc * 64) + r) * HD + c0;
        #pragma unroll
        for (int i = 0; i < 4; i++)
            *(float4*)&s[r][c0 + i * 4] = *(const float4*)(wp + i * 4);
    }
    __syncthreads();
    {
        int n = tid >> 2, k0 = (tid & 3) * 16;
        __nv_bfloat16* dh = g_wth + ((size_t)m * HD + n) * C_ + kc * 64 + k0;
        __nv_bfloat16* dl = g_wvl + (size_t)n * C_ + kc * 64 + k0;
        #pragma unroll
        for (int i = 0; i < 8; i++) {
            float f0 = s[k0 + 2 * i][n], f1 = s[k0 + 2 * i + 1][n];
            __nv_bfloat16 h0 = __float2bfloat16(f0);
            __nv_bfloat16 h1 = __float2bfloat16(f1);
            __nv_bfloat162 hh = __halves2bfloat162(h0, h1);
            *(uint32_t*)(dh + 2 * i) = *(uint32_t*)&hh;
            if (m == 2)
                *(uint32_t*)(dl + 2 * i) = pk_bf16(
                    f0 - __bfloat162float(h0), f1 - __bfloat162float(h1));
        }
    }
}

// ===========================================================================
// Kernel 1: QKV projection, bf16 mma.sync, pipelined.
// X double-buffered smem (cvt of chunk kc+1 overlaps MMAs of kc);
// W double-buffered cp.async issued AFTER the barrier (no overwrite race).
// Dynamic smem: 2 x (XH+XL 20480) + 2 x (4 arrays x 5120) = 81920 B.
// ===========================================================================
#define XS 40
#define WS 40
#define QX(i) ((i) * 20480)            // XH at +0, XL at +10240 within buf
#define QW_W  40960
#define QW_BYTES 81920

__global__ __launch_bounds__(256) void qkv_tc(const float* __restrict__ x)
{
    extern __shared__ __align__(16) char qsm[];
    const uint32_t smb = smem_u32(qsm);

    const int tid = threadIdx.x;
    const int w = tid >> 5;
    const int lane = tid & 31;
    const int g = lane >> 2;
    const int t = lane & 3;
    const int m0 = w * 16;
    const long row0 = (long)blockIdx.x * 128;

    const int lr = lane & 7, lh = (lane >> 3) & 1, lj = lane >> 4;
    const uint32_t a_lane = (uint32_t)((m0 + lh * 8 + lr) * XS + lj * 8);
    const uint32_t b_lane = (uint32_t)((lj * 8 + lr) * WS + lh * 8);

    const int xr = tid >> 1, xc = (tid & 1) * 16;

    float aq[8][4], ak[8][4], av[8][4];
    #pragma unroll
    for (int j = 0; j < 8; j++)
        #pragma unroll
        for (int i = 0; i < 4; i++) { aq[j][i] = 0; ak[j][i] = 0; av[j][i] = 0; }

    // cvt-store helper (macro-ish lambda)
    auto cvt_store = [&](const float4* Xr, int buf) {
        __nv_bfloat16* XH = (__nv_bfloat16*)(qsm + QX(buf));
        __nv_bfloat16* XL = (__nv_bfloat16*)(qsm + QX(buf) + 10240);
        #pragma unroll
        for (int i = 0; i < 4; i++) {
            float4 v = Xr[i];
            __nv_bfloat16 h0 = __float2bfloat16(v.x);
            __nv_bfloat16 h1 = __float2bfloat16(v.y);
            __nv_bfloat16 h2 = __float2bfloat16(v.z);
            __nv_bfloat16 h3 = __float2bfloat16(v.w);
            __nv_bfloat162 a01 = __halves2bfloat162(h0, h1);
            __nv_bfloat162 a23 = __halves2bfloat162(h2, h3);
            *(uint32_t*)&XH[xr * XS + xc + i * 4]     = *(uint32_t*)&a01;
            *(uint32_t*)&XH[xr * XS + xc + i * 4 + 2] = *(uint32_t*)&a23;
            *(uint32_t*)&XL[xr * XS + xc + i * 4] = pk_bf16(
                v.x - __bfloat162float(h0), v.y - __bfloat162float(h1));
            *(uint32_t*)&XL[xr * XS + xc + i * 4 + 2] = pk_bf16(
                v.z - __bfloat162float(h2), v.w - __bfloat162float(h3));
        }
    };
    auto stage_w = [&](int k0, int buf) {
        #pragma unroll
        for (int f4 = 0; f4 < 4; f4++) {
            int f = tid + f4 * 256;
            int arr = f >> 8, rw = (f >> 2) & 63, sg = f & 3;
            const __nv_bfloat16* src =
                (arr < 3) ? g_wth + ((size_t)arr * HD + rw) * C_ + k0 + sg * 8
                          : g_wvl + (size_t)rw * C_ + k0 + sg * 8;
            cpa16(smb + QW_W + (uint32_t)(buf * 20480 + arr * 5120 +
                                          (rw * WS + sg * 8) * 2), src);
        }
        CPA_COMMIT();
    };

    // ---- prologue ----
    float4 Xr[4];
    {
        const float* xp = x + (row0 + xr) * C_ + xc;
        #pragma unroll
        for (int i = 0; i < 4; i++) Xr[i] = *(const float4*)(xp + i * 4);
    }
    stage_w(0, 0);
    cvt_store(Xr, 0);
    {
        const float* xp = x + (row0 + xr) * C_ + 32 + xc;
        #pragma unroll
        for (int i = 0; i < 4; i++) Xr[i] = *(const float4*)(xp + i * 4);
    }

    for (int kc = 0; kc < 32; kc++) {
        const int cur = kc & 1;
        CPA_WAIT0();              // W(kc) landed (only group pending)
        __syncthreads();          // all warps done MMAs(kc-1); X/W bufs free

        if (kc + 1 < 32) stage_w((kc + 1) * 32, 1 - cur);   // overlaps MMAs(kc)
        if (kc + 1 < 32) cvt_store(Xr, 1 - cur);            // X(kc+1) -> smem
        if (kc + 2 < 32) {
            const float* xp = x + (row0 + xr) * C_ + (kc + 2) * 32 + xc;
            #pragma unroll
            for (int i = 0; i < 4; i++) Xr[i] = *(const float4*)(xp + i * 4);
        }

        const uint32_t xhb = smb + QX(cur);
        const uint32_t xlb = xhb + 10240;
        const uint32_t wq  = smb + QW_W + cur * 20480;
        const uint32_t wk  = wq + 5120;
        const uint32_t wvh = wq + 10240;
        const uint32_t wvl = wq + 15360;

        uint32_t aH[2][4], aL[2][4];
        #pragma unroll
        for (int ks = 0; ks < 2; ks++) {
            ldmx4(aH[ks][0], aH[ks][1], aH[ks][2], aH[ks][3],
                  xhb + 2 * (a_lane + ks * 16));
            ldmx4(aL[ks][0], aL[ks][1], aL[ks][2], aL[ks][3],
                  xlb + 2 * (a_lane + ks * 16));
        }
        #pragma unroll
        for (int ks = 0; ks < 2; ks++) {
            #pragma unroll
            for (int j0 = 0; j0 < 8; j0 += 2) {
                uint32_t off = 2 * (b_lane + (uint32_t)(j0 * 8 * WS + ks * 16));
                uint32_t b0, b1, b2, b3;
                ldmx4(b0, b1, b2, b3, wq + off);
                mma16816(aq[j0], aH[ks], b0, b1);
                mma16816(aq[j0 + 1], aH[ks], b2, b3);
                ldmx4(b0, b1, b2, b3, wk + off);
                mma16816(ak[j0], aH[ks], b0, b1);
                mma16816(ak[j0 + 1], aH[ks], b2, b3);
                ldmx4(b0, b1, b2, b3, wvh + off);
                mma16816(av[j0], aH[ks], b0, b1);
                mma16816(av[j0], aL[ks], b0, b1);
                mma16816(av[j0 + 1], aH[ks], b2, b3);
                mma16816(av[j0 + 1], aL[ks], b2, b3);
                ldmx4(b0, b1, b2, b3, wvl + off);
                mma16816(av[j0], aH[ks], b0, b1);
                mma16816(av[j0 + 1], aH[ks], b2, b3);
            }
        }
    }

    // epilogue: q,k -> bf16; v -> fp32
    #pragma unroll
    for (int j = 0; j < 8; j++) {
        int col = 8 * j + 2 * t;
        size_t r0 = (size_t)(row0 + m0 + g) * HD + col;
        size_t r8 = (size_t)(row0 + m0 + g + 8) * HD + col;
        *(uint32_t*)&g_qh[r0] = pk_bf16(aq[j][0], aq[j][1]);
        *(uint32_t*)&g_qh[r8] = pk_bf16(aq[j][2], aq[j][3]);
        *(uint32_t*)&g_kh[r0] = pk_bf16(ak[j][0], ak[j][1]);
        *(uint32_t*)&g_kh[r8] = pk_bf16(ak[j][2], ak[j][3]);
        *(float2*)&g_v[r0] = make_float2(av[j][0], av[j][1]);
        *(float2*)&g_v[r8] = make_float2(av[j][2], av[j][3]);
    }
}

// ===========================================================================
// Kernel 1b: transpose + hi/lo split V -> g_vth/g_vtl [b][h][t]
// ===========================================================================
__global__ __launch_bounds__(256) void vt_kernel()
{
    __shared__ float s[64][68];
    const int tid = threadIdx.x;
    const long t0 = (long)blockIdx.x * 64;
    const int b = blockIdx.y;

    {
        int r = tid >> 2, c0 = (tid & 3) * 16;
        const float* vb = g_v + ((size_t)b * T_ + t0 + r) * HD + c0;
        #pragma unroll
        for (int i = 0; i < 4; i++)
            *(float4*)&s[r][c0 + i * 4] = *(const float4*)(vb + i * 4);
    }
    __syncthreads();
    {
        int h = tid >> 2, ts = (tid & 3) * 16;
        __nv_bfloat16* dh = g_vth + ((size_t)b * HD + h) * T_ + t0 + ts;
        __nv_bfloat16* dl = g_vtl + ((size_t)b * HD + h) * T_ + t0 + ts;
        #pragma unroll
        for (int i = 0; i < 8; i++) {
            float f0 = s[ts + 2 * i][h], f1 = s[ts + 2 * i + 1][h];
            __nv_bfloat16 h0 = __float2bfloat16(f0);
            __nv_bfloat16 h1 = __float2bfloat16(f1);
            __nv_bfloat162 hh = __halves2bfloat162(h0, h1);
            *(uint32_t*)(dh + 2 * i) = *(uint32_t*)&hh;
            *(uint32_t*)(dl + 2 * i) = pk_bf16(
                f0 - __bfloat162float(h0), f1 - __bfloat162float(h1));
        }
    }
}

// ===========================================================================
// Kernel 2: bf16 flash attention, 2-stage compute pipeline:
// QK(jt+1) issues alongside softmax(jt)/PV(jt); 3-deep K/VH/VL cp.async ring
// (prefetch distance 2). Dynamic smem: QS + 3x(K,VH,VL)@64x72 bf16 = 92160 B.
// ===========================================================================
#define LDW 72
#define ORED_LD 68
#define A_QS 0
#define A_K(i)  (9216 + (i) * 9216)
#define A_VH(i) (36864 + (i) * 9216)
#define A_VL(i) (64512 + (i) * 9216)
#define A_BYTES 92160

__global__ __launch_bounds__(256, 1) void attn_mma(float* __restrict__ out)
{
    extern __shared__ __align__(16) char dsm[];
    const uint32_t smb = smem_u32(dsm);

    float* Ored = (float*)(dsm + A_K(0));           // epilogue overlay
    float* lred = Ored + 64 * ORED_LD;

    const int tid = threadIdx.x;
    const int w = tid >> 5;
    const int lane = tid & 31;
    const int g = lane >> 2;
    const int t = lane & 3;
    const int m0 = (w & 3) * 16;
    const int kh = w >> 2;
    const int p = blockIdx.x;
    const int b = blockIdx.y;
    const float scale = 0.03125f;

    const int sr = tid >> 2, sc = (tid & 3) * 16;

    const int lr = lane & 7;
    const int lh = (lane >> 3) & 1;
    const int lj = lane >> 4;
    const uint32_t q_lane  = (uint32_t)((m0 + lh * 8 + lr) * LDW + lj * 8);
    const uint32_t qk_lane = (uint32_t)((kh * 32 + lj * 8 + lr) * LDW + lh * 8);
    const uint32_t pv_lane = (uint32_t)((lj * 8 + lr) * LDW + kh * 32 + lh * 8);

    // stage tile jt into ring slot s (K + VH + VL), one commit group
    auto stage_tile = [&](int s, int jt) {
        const __nv_bfloat16* kb = g_kh + ((size_t)b * T_ + jt * 64 + sr) * HD + sc;
        cpa16(smb + A_K(s) + (uint32_t)((sr * LDW + sc) * 2), kb);
        cpa16(smb + A_K(s) + (uint32_t)((sr * LDW + sc + 8) * 2), kb + 8);
        const __nv_bfloat16* vh = g_vth + ((size_t)b * HD + sr) * T_ + jt * 64 + sc;
        cpa16(smb + A_VH(s) + (uint32_t)((sr * LDW + sc) * 2), vh);
        cpa16(smb + A_VH(s) + (uint32_t)((sr * LDW + sc + 8) * 2), vh + 8);
        const __nv_bfloat16* vl = g_vtl + ((size_t)b * HD + sr) * T_ + jt * 64 + sc;
        cpa16(smb + A_VL(s) + (uint32_t)((sr * LDW + sc) * 2), vl);
        cpa16(smb + A_VL(s) + (uint32_t)((sr * LDW + sc + 8) * 2), vl + 8);
        CPA_COMMIT();
    };
    // QK into given S array from ring slot s
    auto qk_tile = [&](float Sd[4][4], const uint32_t aQ[4][4], int s) {
        const uint32_t ksb = smb + (uint32_t)A_K(s);
        #pragma unroll
        for (int j = 0; j < 4; j++)
            #pragma unroll
            for (int i = 0; i < 4; i++) Sd[j][i] = 0.0f;
        #pragma unroll
        for (int ks = 0; ks < 4; ks++) {
            #pragma unroll
            for (int j0 = 0; j0 < 4; j0 += 2) {
                uint32_t b0, b1, b2, b3;
                ldmx4(b0, b1, b2, b3,
                      ksb + 2 * (qk_lane + (uint32_t)(j0 * 8 * LDW + ks * 16)));
                mma16816(Sd[j0], aQ[ks], b0, b1);
                mma16816(Sd[j0 + 1], aQ[ks], b2, b3);
            }
        }
    };

    for (int half = 0; half < 2; half++) {
        const int it = (half == 0) ? (63 - p) : p;
        const int njt = it + 1;
        const int qrow0 = it * 64 + m0 + g;
        const int qrow8 = qrow0 + 8;

        // ---- prologue: Q + tile0 (group), tile1 (group) ----
        {
            const __nv_bfloat16* qb = g_qh + ((size_t)b * T_ + it * 64 + sr) * HD + sc;
            cpa16(smb + A_QS + (uint32_t)((sr * LDW + sc) * 2), qb);
            cpa16(smb + A_QS + (uint32_t)((sr * LDW + sc + 8) * 2), qb + 8);
        }
        stage_tile(0, 0);                    // group: Q + tile0
        if (njt > 1) { stage_tile(1, 1); CPA_WAIT1(); }
        else CPA_WAIT0();
        __syncthreads();

        uint32_t aQ[4][4];
        #pragma unroll
        for (int ks = 0; ks < 4; ks++)
            ldmx4(aQ[ks][0], aQ[ks][1], aQ[ks][2], aQ[ks][3],
                  smb + A_QS + 2 * (q_lane + ks * 16));

        float S[4][4];
        qk_tile(S, aQ, 0);                   // S(0)

        float O[8][4];
        #pragma unroll
        for (int j = 0; j < 8; j++)
            #pragma unroll
            for (int i = 0; i < 4; i++) O[j][i] = 0.0f;
        float l_g = 0.0f, l_g8 = 0.0f;

        for (int jt = 0; jt < njt; jt++) {
            __syncthreads();    // all warps done with tile jt-1 reads
            const bool have_next = (jt + 1 < njt);
            if (jt + 2 < njt) stage_tile((jt + 2) % 3, jt + 2);
            if (have_next) {
                if (jt + 2 < njt) CPA_WAIT1(); else CPA_WAIT0();
            }
            __syncthreads();    // tile jt+1 visible to all warps

            // ---- QK(jt+1) (independent) — issues alongside softmax below ----
            float S2[4][4];
            if (have_next) qk_tile(S2, aQ, (jt + 1) % 3);

            // ---- softmax(S(jt)) ----
            const int kb0 = jt * 64 + kh * 32;
            const bool dm = (kb0 + 31) > qrow0;
            #pragma unroll
            for (int j = 0; j < 4; j++) {
                int k0 = kb0 + 8 * j + 2 * t;
                float p0 = __expf(S[j][0] * scale);
                float p1 = __expf(S[j][1] * scale);
                float p2 = __expf(S[j][2] * scale);
                float p3 = __expf(S[j][3] * scale);
                if (dm) {
                    if (k0 > qrow0)     p0 = 0.0f;
                    if (k0 + 1 > qrow0) p1 = 0.0f;
                    if (k0 > qrow8)     p2 = 0.0f;
                    if (k0 + 1 > qrow8) p3 = 0.0f;
                }
                S[j][0] = p0; S[j][1] = p1; S[j][2] = p2; S[j][3] = p3;
                l_g  += p0 + p1;
                l_g8 += p2 + p3;
            }

            // ---- pack P hi/lo ----
            uint32_t aH[2][4], aL[2][4];
            #pragma unroll
            for (int kp = 0; kp < 2; kp++)
                #pragma unroll
                for (int hf = 0; hf < 2; hf++) {
                    float* sp = S[2 * kp + hf];
                    #pragma unroll
                    for (int rr = 0; rr < 2; rr++) {
                        float p0 = sp[2 * rr], p1 = sp[2 * rr + 1];
                        __nv_bfloat16 h0 = __float2bfloat16(p0);
                        __nv_bfloat16 h1 = __float2bfloat16(p1);
                        __nv_bfloat162 hh = __halves2bfloat162(h0, h1);
                        aH[kp][hf * 2 + rr] = *(uint32_t*)&hh;
                        aL[kp][hf * 2 + rr] = pk_bf16(
                            p0 - __bfloat162float(h0), p1 - __bfloat162float(h1));
                    }
                }

            // ---- O += Phi Vhi + Plo Vhi + Phi Vlo from ring slot jt%3 ----
            const uint32_t vhb = smb + (uint32_t)A_VH(jt % 3);
            const uint32_t vlb = smb + (uint32_t)A_VL(jt % 3);
            #pragma unroll
            for (int ks = 0; ks < 2; ks++) {
                #pragma unroll
                for (int j0 = 0; j0 < 8; j0 += 2) {
                    uint32_t off = 2 * (pv_lane + (uint32_t)(j0 * 8 * LDW + ks * 16));
                    uint32_t h0, h1, h2, h3, l0, l1, l2, l3;
                    ldmx4(h0, h1, h2, h3, vhb + off);
                    ldmx4(l0, l1, l2, l3, vlb + off);
                    mma16816(O[j0], aH[ks], h0, h1);
                    mma16816(O[j0], aL[ks], h0, h1);
                    mma16816(O[j0], aH[ks], l0, l1);
                    mma16816(O[j0 + 1], aH[ks], h2, h3);
                    mma16816(O[j0 + 1], aL[ks], h2, h3);
                    mma16816(O[j0 + 1], aH[ks], l2, l3);
                }
            }

            // rotate S <- S2
            if (have_next) {
                #pragma unroll
                for (int j = 0; j < 4; j++)
                    #pragma unroll
                    for (int i = 0; i < 4; i++) S[j][i] = S2[j][i];
            }
        }

        // ---- reduce l across quad ----
        l_g  += __shfl_xor_sync(0xffffffffu, l_g, 1);
        l_g  += __shfl_xor_sync(0xffffffffu, l_g, 2);
        l_g8 += __shfl_xor_sync(0xffffffffu, l_g8, 1);
        l_g8 += __shfl_xor_sync(0xffffffffu, l_g8, 2);

        __syncthreads();   // all smem reads done before Ored overlay

        if (kh == 1) {
            #pragma unroll
            for (int j = 0; j < 8; j++) {
                int col = 8 * j + 2 * t;
                *(float2*)&Ored[(m0 + g) * ORED_LD + col] = make_float2(O[j][0], O[j][1]);
                *(float2*)&Ored[(m0 + g + 8) * ORED_LD + col] = make_float2(O[j][2], O[j][3]);
            }
            if (t == 0) { lred[m0 + g] = l_g; lred[m0 + g + 8] = l_g8; }
        }
        __syncthreads();

        if (kh == 0) {
            const float il0 = 1.0f / (l_g + lred[m0 + g]);
            const float il1 = 1.0f / (l_g8 + lred[m0 + g + 8]);
            float* ob = out + ((size_t)b * T_ + (size_t)it * 64 + m0) * HD;
            #pragma unroll
            for (int j = 0; j < 8; j++) {
                int col = 8 * j + 2 * t;
                float2 p0 = *(float2*)&Ored[(m0 + g) * ORED_LD + col];
                float2 p1 = *(float2*)&Ored[(m0 + g + 8) * ORED_LD + col];
                *(float2*)&ob[g * HD + col] =
                    make_float2((O[j][0] + p0.x) * il0, (O[j][1] + p0.y) * il0);
                *(float2*)&ob[(g + 8) * HD + col] =
                    make_float2((O[j][2] + p1.x) * il1, (O[j][3] + p1.y) * il1);
            }
        }
        __syncthreads();   // overlay reads done before next half re-stages
    }
}

// ===========================================================================
extern "C" void kernel_launch(void* const* d_in, const int* in_sizes, int n_in,
                              void* d_out, int out_size)
{
    const float* x  = (const float*)d_in[0];
    const float* Wq = (const float*)d_in[1];
    const float* Wk = (const float*)d_in[2];
    const float* Wv = (const float*)d_in[3];
    float* out = (float*)d_out;

    cudaFuncSetAttribute(qkv_tc, cudaFuncAttributeMaxDynamicSharedMemorySize,
                         QW_BYTES);
    cudaFuncSetAttribute(attn_mma, cudaFuncAttributeMaxDynamicSharedMemorySize,
                         A_BYTES);

    prep_w<<<dim3(16, 3), 256>>>(Wq, Wk, Wv);
    qkv_tc<<<(B_ * T_) / 128, 256, QW_BYTES>>>(x);
    vt_kernel<<<dim3(T_ / 64, B_), 256>>>();
    attn_mma<<<dim3(32, B_), 256, A_BYTES>>>(out);
}

// round 14
// speedup vs baseline: 1.0543x; 1.0543x over previous
#include <cuda_runtime.h>
#include <cuda_bf16.h>
#include <stdint.h>
#include <math.h>

#define B_ 4
#define T_ 4096
#define C_ 1024
#define HD 64

// scratch (no cudaMalloc allowed)
__device__ __nv_bfloat16 g_qh[B_ * T_ * HD];        // Q bf16 [b*t][h]
__device__ __nv_bfloat16 g_kh[B_ * T_ * HD];        // K bf16 [b*t][h]
__device__ float         g_v [B_ * T_ * HD];        // V fp32 [b*t][h]
__device__ __nv_bfloat16 g_vth[B_ * HD * T_];       // V^T hi bf16 [b][h][t]
__device__ __nv_bfloat16 g_vtl[B_ * HD * T_];       // V^T lo
__device__ __nv_bfloat16 g_wth[3 * HD * C_];        // W^T hi bf16 [m][n][k]
__device__ __nv_bfloat16 g_wvl[HD * C_];            // Wv^T lo
// split-K partials
__device__ float g_o0[B_ * T_ * HD];
__device__ float g_o1[B_ * T_ * HD];
__device__ float g_l0[B_ * T_];
__device__ float g_l1[B_ * T_];

// ---------------------------------------------------------------------------
// helpers
// ---------------------------------------------------------------------------
__device__ __forceinline__ uint32_t smem_u32(const void* p) {
    uint32_t a;
    asm("{ .reg .u64 t; cvta.to.shared.u64 t, %1; cvt.u32.u64 %0, t; }"
        : "=r"(a) : "l"(p));
    return a;
}
__device__ __forceinline__ void mma16816(float* c, const uint32_t* a,
                                         uint32_t b0, uint32_t b1) {
    asm volatile(
        "mma.sync.aligned.m16n8k16.row.col.f32.bf16.bf16.f32 "
        "{%0,%1,%2,%3}, {%4,%5,%6,%7}, {%8,%9}, {%0,%1,%2,%3};"
        : "+f"(c[0]), "+f"(c[1]), "+f"(c[2]), "+f"(c[3])
        : "r"(a[0]), "r"(a[1]), "r"(a[2]), "r"(a[3]), "r"(b0), "r"(b1));
}
__device__ __forceinline__ void ldmx4(uint32_t& r0, uint32_t& r1,
                                      uint32_t& r2, uint32_t& r3, uint32_t addr) {
    asm volatile("ldmatrix.sync.aligned.m8n8.x4.shared.b16 {%0,%1,%2,%3}, [%4];"
                 : "=r"(r0), "=r"(r1), "=r"(r2), "=r"(r3) : "r"(addr));
}
__device__ __forceinline__ uint32_t pk_bf16(float lo, float hi) {
    __nv_bfloat162 h = __floats2bfloat162_rn(lo, hi);
    return *(uint32_t*)&h;
}
__device__ __forceinline__ void cpa16(uint32_t saddr, const void* g) {
    asm volatile("cp.async.cg.shared.global [%0], [%1], 16;"
                 :: "r"(saddr), "l"(g) : "memory");
}
#define CPA_COMMIT() asm volatile("cp.async.commit_group;" ::: "memory")
#define CPA_WAIT0()  asm volatile("cp.async.wait_group 0;" ::: "memory")

// ===========================================================================
// Kernel 0: transpose + bf16-split W -> g_wth [m][n][k], g_wvl (v only)
// ===========================================================================
__global__ __launch_bounds__(256) void prep_w(
    const float* __restrict__ Wq, const float* __restrict__ Wk,
    const float* __restrict__ Wv)
{
    __shared__ float s[64][68];
    const int tid = threadIdx.x;
    const int kc = blockIdx.x;
    const int m = blockIdx.y;
    const float* W = (m == 0) ? Wq : (m == 1) ? Wk : Wv;

    {
        int r = tid >> 2, c0 = (tid & 3) * 16;
        const float* wp = W + ((size_t)(kc * 64) + r) * HD + c0;
        #pragma unroll
        for (int i = 0; i < 4; i++)
            *(float4*)&s[r][c0 + i * 4] = *(const float4*)(wp + i * 4);
    }
    __syncthreads();
    {
        int n = tid >> 2, k0 = (tid & 3) * 16;
        __nv_bfloat16* dh = g_wth + ((size_t)m * HD + n) * C_ + kc * 64 + k0;
        __nv_bfloat16* dl = g_wvl + (size_t)n * C_ + kc * 64 + k0;
        #pragma unroll
        for (int i = 0; i < 8; i++) {
            float f0 = s[k0 + 2 * i][n], f1 = s[k0 + 2 * i + 1][n];
            __nv_bfloat16 h0 = __float2bfloat16(f0);
            __nv_bfloat16 h1 = __float2bfloat16(f1);
            __nv_bfloat162 hh = __halves2bfloat162(h0, h1);
            *(uint32_t*)(dh + 2 * i) = *(uint32_t*)&hh;
            if (m == 2)
                *(uint32_t*)(dl + 2 * i) = pk_bf16(
                    f0 - __bfloat162float(h0), f1 - __bfloat162float(h1));
        }
    }
}

// ===========================================================================
// Kernel 1: QKV projection, bf16 mma.sync, pipelined (unchanged from R13).
// ===========================================================================
#define XS 40
#define WS 40
#define QX(i) ((i) * 20480)
#define QW_W  40960
#define QW_BYTES 81920

__global__ __launch_bounds__(256) void qkv_tc(const float* __restrict__ x)
{
    extern __shared__ __align__(16) char qsm[];
    const uint32_t smb = smem_u32(qsm);

    const int tid = threadIdx.x;
    const int w = tid >> 5;
    const int lane = tid & 31;
    const int g = lane >> 2;
    const int t = lane & 3;
    const int m0 = w * 16;
    const long row0 = (long)blockIdx.x * 128;

    const int lr = lane & 7, lh = (lane >> 3) & 1, lj = lane >> 4;
    const uint32_t a_lane = (uint32_t)((m0 + lh * 8 + lr) * XS + lj * 8);
    const uint32_t b_lane = (uint32_t)((lj * 8 + lr) * WS + lh * 8);

    const int xr = tid >> 1, xc = (tid & 1) * 16;

    float aq[8][4], ak[8][4], av[8][4];
    #pragma unroll
    for (int j = 0; j < 8; j++)
        #pragma unroll
        for (int i = 0; i < 4; i++) { aq[j][i] = 0; ak[j][i] = 0; av[j][i] = 0; }

    auto cvt_store = [&](const float4* Xr, int buf) {
        __nv_bfloat16* XH = (__nv_bfloat16*)(qsm + QX(buf));
        __nv_bfloat16* XL = (__nv_bfloat16*)(qsm + QX(buf) + 10240);
        #pragma unroll
        for (int i = 0; i < 4; i++) {
            float4 v = Xr[i];
            __nv_bfloat16 h0 = __float2bfloat16(v.x);
            __nv_bfloat16 h1 = __float2bfloat16(v.y);
            __nv_bfloat16 h2 = __float2bfloat16(v.z);
            __nv_bfloat16 h3 = __float2bfloat16(v.w);
            __nv_bfloat162 a01 = __halves2bfloat162(h0, h1);
            __nv_bfloat162 a23 = __halves2bfloat162(h2, h3);
            *(uint32_t*)&XH[xr * XS + xc + i * 4]     = *(uint32_t*)&a01;
            *(uint32_t*)&XH[xr * XS + xc + i * 4 + 2] = *(uint32_t*)&a23;
            *(uint32_t*)&XL[xr * XS + xc + i * 4] = pk_bf16(
                v.x - __bfloat162float(h0), v.y - __bfloat162float(h1));
            *(uint32_t*)&XL[xr * XS + xc + i * 4 + 2] = pk_bf16(
                v.z - __bfloat162float(h2), v.w - __bfloat162float(h3));
        }
    };
    auto stage_w = [&](int k0, int buf) {
        #pragma unroll
        for (int f4 = 0; f4 < 4; f4++) {
            int f = tid + f4 * 256;
            int arr = f >> 8, rw = (f >> 2) & 63, sg = f & 3;
            const __nv_bfloat16* src =
                (arr < 3) ? g_wth + ((size_t)arr * HD + rw) * C_ + k0 + sg * 8
                          : g_wvl + (size_t)rw * C_ + k0 + sg * 8;
            cpa16(smb + QW_W + (uint32_t)(buf * 20480 + arr * 5120 +
                                          (rw * WS + sg * 8) * 2), src);
        }
        CPA_COMMIT();
    };

    float4 Xr[4];
    {
        const float* xp = x + (row0 + xr) * C_ + xc;
        #pragma unroll
        for (int i = 0; i < 4; i++) Xr[i] = *(const float4*)(xp + i * 4);
    }
    stage_w(0, 0);
    cvt_store(Xr, 0);
    {
        const float* xp = x + (row0 + xr) * C_ + 32 + xc;
        #pragma unroll
        for (int i = 0; i < 4; i++) Xr[i] = *(const float4*)(xp + i * 4);
    }

    for (int kc = 0; kc < 32; kc++) {
        const int cur = kc & 1;
        CPA_WAIT0();
        __syncthreads();

        if (kc + 1 < 32) stage_w((kc + 1) * 32, 1 - cur);
        if (kc + 1 < 32) cvt_store(Xr, 1 - cur);
        if (kc + 2 < 32) {
            const float* xp = x + (row0 + xr) * C_ + (kc + 2) * 32 + xc;
            #pragma unroll
            for (int i = 0; i < 4; i++) Xr[i] = *(const float4*)(xp + i * 4);
        }

        const uint32_t xhb = smb + QX(cur);
        const uint32_t xlb = xhb + 10240;
        const uint32_t wq  = smb + QW_W + cur * 20480;
        const uint32_t wk  = wq + 5120;
        const uint32_t wvh = wq + 10240;
        const uint32_t wvl = wq + 15360;

        uint32_t aH[2][4], aL[2][4];
        #pragma unroll
        for (int ks = 0; ks < 2; ks++) {
            ldmx4(aH[ks][0], aH[ks][1], aH[ks][2], aH[ks][3],
                  xhb + 2 * (a_lane + ks * 16));
            ldmx4(aL[ks][0], aL[ks][1], aL[ks][2], aL[ks][3],
                  xlb + 2 * (a_lane + ks * 16));
        }
        #pragma unroll
        for (int ks = 0; ks < 2; ks++) {
            #pragma unroll
            for (int j0 = 0; j0 < 8; j0 += 2) {
                uint32_t off = 2 * (b_lane + (uint32_t)(j0 * 8 * WS + ks * 16));
                uint32_t b0, b1, b2, b3;
                ldmx4(b0, b1, b2, b3, wq + off);
                mma16816(aq[j0], aH[ks], b0, b1);
                mma16816(aq[j0 + 1], aH[ks], b2, b3);
                ldmx4(b0, b1, b2, b3, wk + off);
                mma16816(ak[j0], aH[ks], b0, b1);
                mma16816(ak[j0 + 1], aH[ks], b2, b3);
                ldmx4(b0, b1, b2, b3, wvh + off);
                mma16816(av[j0], aH[ks], b0, b1);
                mma16816(av[j0], aL[ks], b0, b1);
                mma16816(av[j0 + 1], aH[ks], b2, b3);
                mma16816(av[j0 + 1], aL[ks], b2, b3);
                ldmx4(b0, b1, b2, b3, wvl + off);
                mma16816(av[j0], aH[ks], b0, b1);
                mma16816(av[j0 + 1], aH[ks], b2, b3);
            }
        }
    }

    #pragma unroll
    for (int j = 0; j < 8; j++) {
        int col = 8 * j + 2 * t;
        size_t r0 = (size_t)(row0 + m0 + g) * HD + col;
        size_t r8 = (size_t)(row0 + m0 + g + 8) * HD + col;
        *(uint32_t*)&g_qh[r0] = pk_bf16(aq[j][0], aq[j][1]);
        *(uint32_t*)&g_qh[r8] = pk_bf16(aq[j][2], aq[j][3]);
        *(uint32_t*)&g_kh[r0] = pk_bf16(ak[j][0], ak[j][1]);
        *(uint32_t*)&g_kh[r8] = pk_bf16(ak[j][2], ak[j][3]);
        *(float2*)&g_v[r0] = make_float2(av[j][0], av[j][1]);
        *(float2*)&g_v[r8] = make_float2(av[j][2], av[j][3]);
    }
}

// ===========================================================================
// Kernel 1b: transpose + hi/lo split V -> g_vth/g_vtl [b][h][t]
// ===========================================================================
__global__ __launch_bounds__(256) void vt_kernel()
{
    __shared__ float s[64][68];
    const int tid = threadIdx.x;
    const long t0 = (long)blockIdx.x * 64;
    const int b = blockIdx.y;

    {
        int r = tid >> 2, c0 = (tid & 3) * 16;
        const float* vb = g_v + ((size_t)b * T_ + t0 + r) * HD + c0;
        #pragma unroll
        for (int i = 0; i < 4; i++)
            *(float4*)&s[r][c0 + i * 4] = *(const float4*)(vb + i * 4);
    }
    __syncthreads();
    {
        int h = tid >> 2, ts = (tid & 3) * 16;
        __nv_bfloat16* dh = g_vth + ((size_t)b * HD + h) * T_ + t0 + ts;
        __nv_bfloat16* dl = g_vtl + ((size_t)b * HD + h) * T_ + t0 + ts;
        #pragma unroll
        for (int i = 0; i < 8; i++) {
            float f0 = s[ts + 2 * i][h], f1 = s[ts + 2 * i + 1][h];
            __nv_bfloat16 h0 = __float2bfloat16(f0);
            __nv_bfloat16 h1 = __float2bfloat16(f1);
            __nv_bfloat162 hh = __halves2bfloat162(h0, h1);
            *(uint32_t*)(dh + 2 * i) = *(uint32_t*)&hh;
            *(uint32_t*)(dl + 2 * i) = pk_bf16(
                f0 - __bfloat162float(h0), f1 - __bfloat162float(h1));
        }
    }
}

// ===========================================================================
// Kernel 2: bf16 flash attention, SPLIT-K: grid (32, B, 2). z-half of key
// tiles per block; O,l accumulate additively -> unnormalized partials to
// g_o{0,1}/g_l{0,1}; combine kernel normalizes. 2-deep cp.async ring (R11
// core, no S2 pipeline). launch_bounds(256,2) -> 2 blocks/SM co-resident.
// Dynamic smem: QS + 2x(K,VH,VL) @ 64x72 bf16 = 64512 B (x2 = 129KB OK).
// ===========================================================================
#define LDW 72
#define ORED_LD 68
#define A_QS 0
#define A_K(i)  (9216 + (i) * 9216)
#define A_VH(i) (27648 + (i) * 9216)
#define A_VL(i) (46080 + (i) * 9216)
#define A_BYTES 64512

__global__ __launch_bounds__(256, 2) void attn_mma()
{
    extern __shared__ __align__(16) char dsm[];
    const uint32_t smb = smem_u32(dsm);

    float* Ored = (float*)(dsm + A_K(0));           // epilogue overlay
    float* lred = Ored + 64 * ORED_LD;

    const int tid = threadIdx.x;
    const int w = tid >> 5;
    const int lane = tid & 31;
    const int g = lane >> 2;
    const int t = lane & 3;
    const int m0 = (w & 3) * 16;
    const int kh = w >> 2;
    const int p = blockIdx.x;
    const int b = blockIdx.y;
    const int z = blockIdx.z;
    const float scale = 0.03125f;

    float* goz = z ? g_o1 : g_o0;
    float* glz = z ? g_l1 : g_l0;

    const int sr = tid >> 2, sc = (tid & 3) * 16;

    const int lr = lane & 7;
    const int lh = (lane >> 3) & 1;
    const int lj = lane >> 4;
    const uint32_t q_lane  = (uint32_t)((m0 + lh * 8 + lr) * LDW + lj * 8);
    const uint32_t qk_lane = (uint32_t)((kh * 32 + lj * 8 + lr) * LDW + lh * 8);
    const uint32_t pv_lane = (uint32_t)((lj * 8 + lr) * LDW + kh * 32 + lh * 8);

    auto stage_tile = [&](int s, int jt) {
        const __nv_bfloat16* kb = g_kh + ((size_t)b * T_ + jt * 64 + sr) * HD + sc;
        cpa16(smb + A_K(s) + (uint32_t)((sr * LDW + sc) * 2), kb);
        cpa16(smb + A_K(s) + (uint32_t)((sr * LDW + sc + 8) * 2), kb + 8);
        const __nv_bfloat16* vh = g_vth + ((size_t)b * HD + sr) * T_ + jt * 64 + sc;
        cpa16(smb + A_VH(s) + (uint32_t)((sr * LDW + sc) * 2), vh);
        cpa16(smb + A_VH(s) + (uint32_t)((sr * LDW + sc + 8) * 2), vh + 8);
        const __nv_bfloat16* vl = g_vtl + ((size_t)b * HD + sr) * T_ + jt * 64 + sc;
        cpa16(smb + A_VL(s) + (uint32_t)((sr * LDW + sc) * 2), vl);
        cpa16(smb + A_VL(s) + (uint32_t)((sr * LDW + sc + 8) * 2), vl + 8);
        CPA_COMMIT();
    };

    for (int half = 0; half < 2; half++) {
        const int it = (half == 0) ? (63 - p) : p;
        const int njt = it + 1;
        const int mid = (njt + 1) >> 1;
        const int lo = z ? mid : 0;
        const int hi = z ? njt : mid;
        const int cnt = hi - lo;
        const int qrow0 = it * 64 + m0 + g;
        const int qrow8 = qrow0 + 8;

        // ---- prologue: Q (+ tile lo) group ----
        {
            const __nv_bfloat16* qb = g_qh + ((size_t)b * T_ + it * 64 + sr) * HD + sc;
            cpa16(smb + A_QS + (uint32_t)((sr * LDW + sc) * 2), qb);
            cpa16(smb + A_QS + (uint32_t)((sr * LDW + sc + 8) * 2), qb + 8);
        }
        if (cnt > 0) stage_tile(0, lo);
        CPA_COMMIT();                 // close group (Q alone if cnt==0)
        CPA_WAIT0();
        __syncthreads();

        uint32_t aQ[4][4];
        #pragma unroll
        for (int ks = 0; ks < 4; ks++)
            ldmx4(aQ[ks][0], aQ[ks][1], aQ[ks][2], aQ[ks][3],
                  smb + A_QS + 2 * (q_lane + ks * 16));

        float O[8][4];
        #pragma unroll
        for (int j = 0; j < 8; j++)
            #pragma unroll
            for (int i = 0; i < 4; i++) O[j][i] = 0.0f;
        float l_g = 0.0f, l_g8 = 0.0f;

        for (int u = 0; u < cnt; u++) {
            const int jt = lo + u;
            const int cur = u & 1;
            if (u > 0) { CPA_WAIT0(); __syncthreads(); }
            if (u + 1 < cnt) stage_tile(1 - cur, jt + 1);   // overlaps compute

            const uint32_t ksb = smb + (uint32_t)A_K(cur);
            const uint32_t vhb = smb + (uint32_t)A_VH(cur);
            const uint32_t vlb = smb + (uint32_t)A_VL(cur);

            // ---- S = Q K^T over this warp's 32-key half ----
            float S[4][4];
            #pragma unroll
            for (int j = 0; j < 4; j++)
                #pragma unroll
                for (int i = 0; i < 4; i++) S[j][i] = 0.0f;
            #pragma unroll
            for (int ks = 0; ks < 4; ks++) {
                #pragma unroll
                for (int j0 = 0; j0 < 4; j0 += 2) {
                    uint32_t b0, b1, b2, b3;
                    ldmx4(b0, b1, b2, b3,
                          ksb + 2 * (qk_lane + (uint32_t)(j0 * 8 * LDW + ks * 16)));
                    mma16816(S[j0], aQ[ks], b0, b1);
                    mma16816(S[j0 + 1], aQ[ks], b2, b3);
                }
            }

            // ---- softmax ----
            const int kb0 = jt * 64 + kh * 32;
            const bool dm = (kb0 + 31) > qrow0;
            #pragma unroll
            for (int j = 0; j < 4; j++) {
                int k0 = kb0 + 8 * j + 2 * t;
                float p0 = __expf(S[j][0] * scale);
                float p1 = __expf(S[j][1] * scale);
                float p2 = __expf(S[j][2] * scale);
                float p3 = __expf(S[j][3] * scale);
                if (dm) {
                    if (k0 > qrow0)     p0 = 0.0f;
                    if (k0 + 1 > qrow0) p1 = 0.0f;
                    if (k0 > qrow8)     p2 = 0.0f;
                    if (k0 + 1 > qrow8) p3 = 0.0f;
                }
                S[j][0] = p0; S[j][1] = p1; S[j][2] = p2; S[j][3] = p3;
                l_g  += p0 + p1;
                l_g8 += p2 + p3;
            }

            // ---- pack P hi/lo ----
            uint32_t aH[2][4], aL[2][4];
            #pragma unroll
            for (int kp = 0; kp < 2; kp++)
                #pragma unroll
                for (int hf = 0; hf < 2; hf++) {
                    float* sp = S[2 * kp + hf];
                    #pragma unroll
                    for (int rr = 0; rr < 2; rr++) {
                        float p0 = sp[2 * rr], p1 = sp[2 * rr + 1];
                        __nv_bfloat16 h0 = __float2bfloat16(p0);
                        __nv_bfloat16 h1 = __float2bfloat16(p1);
                        __nv_bfloat162 hh = __halves2bfloat162(h0, h1);
                        aH[kp][hf * 2 + rr] = *(uint32_t*)&hh;
                        aL[kp][hf * 2 + rr] = pk_bf16(
                            p0 - __bfloat162float(h0), p1 - __bfloat162float(h1));
                    }
                }

            // ---- O += Phi Vhi + Plo Vhi + Phi Vlo ----
            #pragma unroll
            for (int ks = 0; ks < 2; ks++) {
                #pragma unroll
                for (int j0 = 0; j0 < 8; j0 += 2) {
                    uint32_t off = 2 * (pv_lane + (uint32_t)(j0 * 8 * LDW + ks * 16));
                    uint32_t h0, h1, h2, h3, l0, l1, l2, l3;
                    ldmx4(h0, h1, h2, h3, vhb + off);
                    ldmx4(l0, l1, l2, l3, vlb + off);
                    mma16816(O[j0], aH[ks], h0, h1);
                    mma16816(O[j0], aL[ks], h0, h1);
                    mma16816(O[j0], aH[ks], l0, l1);
                    mma16816(O[j0 + 1], aH[ks], h2, h3);
                    mma16816(O[j0 + 1], aL[ks], h2, h3);
                    mma16816(O[j0 + 1], aH[ks], l2, l3);
                }
            }
        }

        // ---- reduce l across quad ----
        l_g  += __shfl_xor_sync(0xffffffffu, l_g, 1);
        l_g  += __shfl_xor_sync(0xffffffffu, l_g, 2);
        l_g8 += __shfl_xor_sync(0xffffffffu, l_g8, 1);
        l_g8 += __shfl_xor_sync(0xffffffffu, l_g8, 2);

        __syncthreads();   // all smem reads done before Ored overlay

        if (kh == 1) {
            #pragma unroll
            for (int j = 0; j < 8; j++) {
                int col = 8 * j + 2 * t;
                *(float2*)&Ored[(m0 + g) * ORED_LD + col] = make_float2(O[j][0], O[j][1]);
                *(float2*)&Ored[(m0 + g + 8) * ORED_LD + col] = make_float2(O[j][2], O[j][3]);
            }
            if (t == 0) { lred[m0 + g] = l_g; lred[m0 + g + 8] = l_g8; }
        }
        __syncthreads();

        if (kh == 0) {
            // write UNNORMALIZED partials + l to split-K scratch
            size_t rbase = (size_t)b * T_ + (size_t)it * 64 + m0;
            float* ob = goz + (rbase) * HD;
            if (t == 0) {
                glz[rbase + g] = l_g + lred[m0 + g];
                glz[rbase + g + 8] = l_g8 + lred[m0 + g + 8];
            }
            #pragma unroll
            for (int j = 0; j < 8; j++) {
                int col = 8 * j + 2 * t;
                float2 p0 = *(float2*)&Ored[(m0 + g) * ORED_LD + col];
                float2 p1 = *(float2*)&Ored[(m0 + g + 8) * ORED_LD + col];
                *(float2*)&ob[g * HD + col] =
                    make_float2(O[j][0] + p0.x, O[j][1] + p0.y);
                *(float2*)&ob[(g + 8) * HD + col] =
                    make_float2(O[j][2] + p1.x, O[j][3] + p1.y);
            }
        }
        __syncthreads();   // overlay reads done before next half re-stages
    }
}

// ===========================================================================
// Kernel 3: combine split-K partials: out = (O0 + O1) / (l0 + l1)
// ===========================================================================
__global__ __launch_bounds__(256) void combine(float* __restrict__ out)
{
    const int tid = threadIdx.x;
    const size_t r = (size_t)blockIdx.x * 64 + (tid >> 2);
    const int c0 = (tid & 3) * 16;
    const float inv = 1.0f / (g_l0[r] + g_l1[r]);
    const float* o0 = g_o0 + r * HD + c0;
    const float* o1 = g_o1 + r * HD + c0;
    float* ob = out + r * HD + c0;
    #pragma unroll
    for (int i = 0; i < 4; i++) {
        float4 a = *(const float4*)(o0 + i * 4);
        float4 bb = *(const float4*)(o1 + i * 4);
        *(float4*)(ob + i * 4) = make_float4((a.x + bb.x) * inv, (a.y + bb.y) * inv,
                                             (a.z + bb.z) * inv, (a.w + bb.w) * inv);
    }
}

// ===========================================================================
extern "C" void kernel_launch(void* const* d_in, const int* in_sizes, int n_in,
                              void* d_out, int out_size)
{
    const float* x  = (const float*)d_in[0];
    const float* Wq = (const float*)d_in[1];
    const float* Wk = (const float*)d_in[2];
    const float* Wv = (const float*)d_in[3];
    float* out = (float*)d_out;

    cudaFuncSetAttribute(qkv_tc, cudaFuncAttributeMaxDynamicSharedMemorySize,
                         QW_BYTES);
    cudaFuncSetAttribute(attn_mma, cudaFuncAttributeMaxDynamicSharedMemorySize,
                         A_BYTES);

    prep_w<<<dim3(16, 3), 256>>>(Wq, Wk, Wv);
    qkv_tc<<<(B_ * T_) / 128, 256, QW_BYTES>>>(x);
    vt_kernel<<<dim3(T_ / 64, B_), 256>>>();
    attn_mma<<<dim3(32, B_, 2), 256, A_BYTES>>>();
    combine<<<(B_ * T_) / 64, 256>>>(out);
}